// round 1
// baseline (speedup 1.0000x reference)
#include <cuda_runtime.h>
#include <math.h>

#define BB 8
#define SS 1024
#define DD 512
#define HH 8
#define DKK 64
#define DFFN 2048
#define MROWS (BB*SS)          /* 8192 */
#define SD (SS*DD)             /* 524288 */

// ---------------- scratch (static device globals; no runtime alloc) --------
__device__ float g_q  [MROWS*DD];
__device__ float g_k  [MROWS*DD];
__device__ float g_v  [MROWS*DD];
__device__ float g_att[MROWS*DD];
__device__ float g_res[MROWS*DD];
__device__ float g_x1 [MROWS*DD];
__device__ float g_x2 [MROWS*DD];
__device__ float g_ff [MROWS*DFFN];
__device__ float g_psum  [BB*256];
__device__ float g_psumsq[BB*256];
__device__ float g_mr[2*BB];

// ---------------- GEMM: C[M,N] = A[M,K] @ W' + epilogue --------------------
// BMODE 0: "HEADS"  W is [H, K, 64]; logical B[kk][n] = W[(n>>6)*K*64 + kk*64 + (n&63)]
// BMODE 1: "TRANS"  W is [N, K];     logical B[kk][n] = W[n*K + kk]
// EPI 0: +bias[n] ; EPI 1: +bias[n]+resid[m,n] ; EPI 2: relu(+bias[n])
template<int BMODE, int EPI>
__global__ void __launch_bounds__(256) gemm_kernel(
    const float* __restrict__ A, const float* __restrict__ W,
    const float* __restrict__ bias, const float* __restrict__ resid,
    float* __restrict__ C, int M, int N, int K)
{
    __shared__ float As[16][128];
    __shared__ float Bs[16][128];
    const int bm = blockIdx.y * 128;
    const int bn = blockIdx.x * 128;
    const int tid = threadIdx.x;
    const int tr = (tid >> 4) << 3;   // 0..120
    const int tc = (tid & 15) << 3;   // 0..120

    float acc[8][8];
#pragma unroll
    for (int i = 0; i < 8; i++)
#pragma unroll
        for (int j = 0; j < 8; j++) acc[i][j] = 0.f;

    const int ar = tid >> 2;          // 0..63
    const int ak = (tid & 3) << 2;    // 0,4,8,12

    for (int k0 = 0; k0 < K; k0 += 16) {
        // ---- load A tile (128x16) ----
#pragma unroll
        for (int i = 0; i < 2; i++) {
            int r = ar + i * 64;
            float4 a = *reinterpret_cast<const float4*>(
                &A[(size_t)(bm + r) * K + k0 + ak]);
            As[ak + 0][r] = a.x; As[ak + 1][r] = a.y;
            As[ak + 2][r] = a.z; As[ak + 3][r] = a.w;
        }
        // ---- load B tile (16x128) ----
        if (BMODE == 0) {
            int kk = tid >> 4;            // 0..15
            int n  = (tid & 15) << 3;     // 0..120
            int gn = bn + n;
            const float* wp = &W[(size_t)(gn >> 6) * (size_t)K * 64
                                 + (size_t)(k0 + kk) * 64 + (gn & 63)];
            float4 b0 = *reinterpret_cast<const float4*>(wp);
            float4 b1 = *reinterpret_cast<const float4*>(wp + 4);
            Bs[kk][n + 0] = b0.x; Bs[kk][n + 1] = b0.y;
            Bs[kk][n + 2] = b0.z; Bs[kk][n + 3] = b0.w;
            Bs[kk][n + 4] = b1.x; Bs[kk][n + 5] = b1.y;
            Bs[kk][n + 6] = b1.z; Bs[kk][n + 7] = b1.w;
        } else {
#pragma unroll
            for (int i = 0; i < 2; i++) {
                int n = (tid >> 2) + i * 64;
                float4 b = *reinterpret_cast<const float4*>(
                    &W[(size_t)(bn + n) * K + k0 + ak]);
                Bs[ak + 0][n] = b.x; Bs[ak + 1][n] = b.y;
                Bs[ak + 2][n] = b.z; Bs[ak + 3][n] = b.w;
            }
        }
        __syncthreads();
        // ---- compute ----
#pragma unroll
        for (int kk = 0; kk < 16; kk++) {
            float4 a0 = *reinterpret_cast<const float4*>(&As[kk][tr]);
            float4 a1 = *reinterpret_cast<const float4*>(&As[kk][tr + 4]);
            float4 b0 = *reinterpret_cast<const float4*>(&Bs[kk][tc]);
            float4 b1 = *reinterpret_cast<const float4*>(&Bs[kk][tc + 4]);
            float ra[8] = {a0.x, a0.y, a0.z, a0.w, a1.x, a1.y, a1.z, a1.w};
            float rb[8] = {b0.x, b0.y, b0.z, b0.w, b1.x, b1.y, b1.z, b1.w};
#pragma unroll
            for (int i = 0; i < 8; i++)
#pragma unroll
                for (int j = 0; j < 8; j++)
                    acc[i][j] += ra[i] * rb[j];
        }
        __syncthreads();
    }
    // ---- epilogue ----
#pragma unroll
    for (int i = 0; i < 8; i++) {
        int row = bm + tr + i;
#pragma unroll
        for (int j = 0; j < 8; j++) {
            int col = bn + tc + j;
            float v = acc[i][j] + bias[col];
            if (EPI == 2) v = fmaxf(v, 0.f);
            if (EPI == 1) v += resid[(size_t)row * N + col];
            C[(size_t)row * N + col] = v;
        }
    }
}

// ---------------- attention: flash-style, 1 warp = 1 query ------------------
// Q,K,V layout: [B,S, H*64]; O same. mask: [B,S] over keys.
__global__ void __launch_bounds__(256) attn_kernel(
    const float* __restrict__ Q, const float* __restrict__ K,
    const float* __restrict__ V, const int* __restrict__ mask,
    float* __restrict__ O)
{
    __shared__ float q_s[8][64];
    __shared__ float k_s[32][65];
    __shared__ float v_s[32][65];
    __shared__ float p_s[8][32];
    __shared__ int   m_s[32];

    const int bh = blockIdx.x;
    const int b = bh >> 3, h = bh & 7;
    const int q0 = blockIdx.y * 8;
    const int tid = threadIdx.x;
    const int w = tid >> 5, lane = tid & 31;

#pragma unroll
    for (int i = 0; i < 2; i++) {
        int idx = tid + i * 256;
        int r = idx >> 6, d = idx & 63;
        q_s[r][d] = Q[(size_t)(b * SS + q0 + r) * 512 + h * 64 + d];
    }

    float m = -INFINITY, l = 0.f, o0 = 0.f, o1 = 0.f;

    for (int kc = 0; kc < SS; kc += 32) {
        __syncthreads();
#pragma unroll
        for (int i = 0; i < 8; i++) {
            int idx = tid + i * 256;
            int r = idx >> 6, d = idx & 63;
            size_t g = (size_t)(b * SS + kc + r) * 512 + h * 64 + d;
            k_s[r][d] = K[g];
            v_s[r][d] = V[g];
        }
        if (tid < 32) m_s[tid] = mask[b * SS + kc + tid];
        __syncthreads();

        float s = 0.f;
#pragma unroll
        for (int d = 0; d < 64; d++) s += q_s[w][d] * k_s[lane][d];
        s *= 0.125f;
        if (m_s[lane] == 0) s = -1e10f;

        float mx = s;
#pragma unroll
        for (int o = 16; o; o >>= 1)
            mx = fmaxf(mx, __shfl_xor_sync(0xffffffffu, mx, o));
        float m_new = fmaxf(m, mx);
        float scale = __expf(m - m_new);        // m=-inf first iter -> 0
        float p = __expf(s - m_new);
        float ps = p;
#pragma unroll
        for (int o = 16; o; o >>= 1)
            ps += __shfl_xor_sync(0xffffffffu, ps, o);
        l = l * scale + ps;
        o0 *= scale; o1 *= scale;
        p_s[w][lane] = p;
        __syncwarp();
#pragma unroll
        for (int j = 0; j < 32; j++) {
            float pj = p_s[w][j];
            o0 += pj * v_s[j][lane];
            o1 += pj * v_s[j][lane + 32];
        }
        m = m_new;
    }
    float inv = 1.f / l;
    size_t ob = (size_t)(b * SS + q0 + w) * 512 + h * 64;
    O[ob + lane]      = o0 * inv;
    O[ob + lane + 32] = o1 * inv;
}

// ---------------- LayerNorm over [S,D] per batch ---------------------------
__global__ void __launch_bounds__(256) ln_partial_kernel(const float* __restrict__ X)
{
    int b = blockIdx.x >> 8;
    int c = blockIdx.x & 255;
    int tid = threadIdx.x;
    const float* p = X + (size_t)b * SD + (size_t)c * 2048;
    float s = 0.f, s2 = 0.f;
#pragma unroll
    for (int i = 0; i < 8; i++) {
        float v = p[tid + i * 256];
        s += v; s2 += v * v;
    }
    __shared__ float sh[256], sh2[256];
    sh[tid] = s; sh2[tid] = s2;
    __syncthreads();
    for (int o = 128; o; o >>= 1) {
        if (tid < o) { sh[tid] += sh[tid + o]; sh2[tid] += sh2[tid + o]; }
        __syncthreads();
    }
    if (tid == 0) { g_psum[blockIdx.x] = sh[0]; g_psumsq[blockIdx.x] = sh2[0]; }
}

__global__ void __launch_bounds__(256) ln_final_kernel()
{
    int b = blockIdx.x;
    int tid = threadIdx.x;
    __shared__ float sh[256], sh2[256];
    sh[tid] = g_psum[b * 256 + tid];
    sh2[tid] = g_psumsq[b * 256 + tid];
    __syncthreads();
    for (int o = 128; o; o >>= 1) {
        if (tid < o) { sh[tid] += sh[tid + o]; sh2[tid] += sh2[tid + o]; }
        __syncthreads();
    }
    if (tid == 0) {
        float inv_n = 1.f / (float)SD;
        float mean = sh[0] * inv_n;
        float var = sh2[0] * inv_n - mean * mean;
        g_mr[2 * b] = mean;
        g_mr[2 * b + 1] = rsqrtf(var + 1e-6f);
    }
}

__global__ void __launch_bounds__(256) ln_apply_kernel(
    const float* __restrict__ X, const float* __restrict__ w,
    const float* __restrict__ bb, float* __restrict__ Y)
{
    int i4 = blockIdx.x * 256 + threadIdx.x;     // 4 floats per thread
    size_t base = (size_t)i4 * 4;
    int b = (int)(base / SD);
    size_t sd = base % SD;
    float mean = g_mr[2 * b], rstd = g_mr[2 * b + 1];
    float4 xv = *reinterpret_cast<const float4*>(X + base);
    float4 wv = *reinterpret_cast<const float4*>(w + sd);
    float4 bv = *reinterpret_cast<const float4*>(bb + sd);
    float4 yv;
    yv.x = (xv.x - mean) * rstd * wv.x + bv.x;
    yv.y = (xv.y - mean) * rstd * wv.y + bv.y;
    yv.z = (xv.z - mean) * rstd * wv.z + bv.z;
    yv.w = (xv.w - mean) * rstd * wv.w + bv.w;
    *reinterpret_cast<float4*>(Y + base) = yv;
}

// ---------------- driver ---------------------------------------------------
static void run_ln(const float* X, const float* w, const float* b, float* Y)
{
    ln_partial_kernel<<<BB * 256, 256>>>(X);
    ln_final_kernel<<<BB, 256>>>();
    ln_apply_kernel<<<SD * BB / 1024, 256>>>(X, w, b, Y);
}

extern "C" void kernel_launch(void* const* d_in, const int* in_sizes, int n_in,
                              void* d_out, int out_size)
{
    const float* x        = (const float*)d_in[0];
    const float* y        = (const float*)d_in[1];
    const int*   src_mask = (const int*)  d_in[2];
    const int*   trg_mask = (const int*)  d_in[3];
    const float* m1_wq = (const float*)d_in[4];
    const float* m1_bq = (const float*)d_in[5];
    const float* m1_wk = (const float*)d_in[6];
    const float* m1_bk = (const float*)d_in[7];
    const float* m1_wv = (const float*)d_in[8];
    const float* m1_bv = (const float*)d_in[9];
    const float* m1_wo = (const float*)d_in[10];
    const float* m1_bo = (const float*)d_in[11];
    const float* m2_wq = (const float*)d_in[12];
    const float* m2_bq = (const float*)d_in[13];
    const float* m2_wk = (const float*)d_in[14];
    const float* m2_bk = (const float*)d_in[15];
    const float* m2_wv = (const float*)d_in[16];
    const float* m2_bv = (const float*)d_in[17];
    const float* m2_wo = (const float*)d_in[18];
    const float* m2_bo = (const float*)d_in[19];
    const float* pw1   = (const float*)d_in[20];
    const float* pb1   = (const float*)d_in[21];
    const float* pw2   = (const float*)d_in[22];
    const float* pb2   = (const float*)d_in[23];
    const float* ln1_w = (const float*)d_in[24];
    const float* ln1_b = (const float*)d_in[25];
    const float* ln2_w = (const float*)d_in[26];
    const float* ln2_b = (const float*)d_in[27];
    const float* ln3_w = (const float*)d_in[28];
    const float* ln3_b = (const float*)d_in[29];
    float* out = (float*)d_out;

    float *q, *k, *v, *att, *res, *x1, *x2, *ff;
    cudaGetSymbolAddress((void**)&q,   g_q);
    cudaGetSymbolAddress((void**)&k,   g_k);
    cudaGetSymbolAddress((void**)&v,   g_v);
    cudaGetSymbolAddress((void**)&att, g_att);
    cudaGetSymbolAddress((void**)&res, g_res);
    cudaGetSymbolAddress((void**)&x1,  g_x1);
    cudaGetSymbolAddress((void**)&x2,  g_x2);
    cudaGetSymbolAddress((void**)&ff,  g_ff);

    dim3 gProj(4, 64);       // N=512
    dim3 gFf1(16, 64);       // N=2048
    dim3 gAttn(BB * HH, SS / 8);

    // ---- stage 1: self-attention ----
    gemm_kernel<0, 0><<<gProj, 256>>>(x, m1_wq, m1_bq, nullptr, q, MROWS, 512, 512);
    gemm_kernel<0, 0><<<gProj, 256>>>(x, m1_wk, m1_bk, nullptr, k, MROWS, 512, 512);
    gemm_kernel<0, 0><<<gProj, 256>>>(x, m1_wv, m1_bv, nullptr, v, MROWS, 512, 512);
    attn_kernel<<<gAttn, 256>>>(q, k, v, trg_mask, att);
    gemm_kernel<1, 1><<<gProj, 256>>>(att, m1_wo, m1_bo, x, res, MROWS, 512, 512);
    run_ln(res, ln1_w, ln1_b, x1);

    // ---- stage 2: cross-attention ----
    gemm_kernel<0, 0><<<gProj, 256>>>(x1, m2_wq, m2_bq, nullptr, q, MROWS, 512, 512);
    gemm_kernel<0, 0><<<gProj, 256>>>(y,  m2_wk, m2_bk, nullptr, k, MROWS, 512, 512);
    gemm_kernel<0, 0><<<gProj, 256>>>(y,  m2_wv, m2_bv, nullptr, v, MROWS, 512, 512);
    attn_kernel<<<gAttn, 256>>>(q, k, v, src_mask, att);
    gemm_kernel<1, 1><<<gProj, 256>>>(att, m2_wo, m2_bo, x1, res, MROWS, 512, 512);
    run_ln(res, ln2_w, ln2_b, x2);

    // ---- stage 3: FFN ----
    gemm_kernel<1, 2><<<gFf1, 256>>>(x2, pw1, pb1, nullptr, ff, MROWS, DFFN, 512);
    gemm_kernel<1, 1><<<gProj, 256>>>(ff, pw2, pb2, x2, res, MROWS, 512, DFFN);
    run_ln(res, ln3_w, ln3_b, out);
}